// round 12
// baseline (speedup 1.0000x reference)
#include <cuda_runtime.h>

typedef unsigned long long u64;

#define THREADS 128
#define NPTS 3                          // points per thread
#define PTS_PER_BLOCK (THREADS * NPTS)
#define HIDDEN 16
#define NLAYERS 8

// ---------- f32x2 packed-math helpers (sm_103a) ----------
__device__ __forceinline__ void unpack2(u64 a, float& lo, float& hi) {
    asm("mov.b64 {%0, %1}, %2;" : "=f"(lo), "=f"(hi) : "l"(a));
}
__device__ __forceinline__ u64 dup2(float s) {  // (s, s)
    u64 r; asm("mov.b64 %0, {%1, %1};" : "=l"(r) : "f"(s)); return r;
}
__device__ __forceinline__ u64 ffma2(u64 a, u64 b, u64 c) {
    u64 d; asm("fma.rn.f32x2 %0, %1, %2, %3;" : "=l"(d) : "l"(a), "l"(b), "l"(c)); return d;
}
__device__ __forceinline__ u64 fmul2(u64 a, u64 b) {
    u64 d; asm("mul.rn.f32x2 %0, %1, %2;" : "=l"(d) : "l"(a), "l"(b)); return d;
}
__device__ __forceinline__ float tanh_hw(float x) {
    float r; asm("tanh.approx.f32 %0, %1;" : "=f"(r) : "f"(x)); return r;
}
__device__ __forceinline__ float sigmoid_hw(float x) {
    // sigmoid(x) = 0.5*tanh(0.5x)+0.5
    return fmaf(tanh_hw(0.5f * x), 0.5f, 0.5f);
}

__global__ void __launch_bounds__(THREADS, 4)
mlp_kernel(const float* __restrict__ x,
           const float* __restrict__ W_in,
           const float* __restrict__ b_in,
           const float* __restrict__ W_h,
           const float* __restrict__ W_out,
           float* __restrict__ out,
           int n_points)
{
    // Transposed weights, plain f32. Row k of layer l = 16 contiguous floats
    // = 4 ulonglong2 -> broadcast LDS.128 (conflict-free).
    __shared__ __align__(16) float sWh_t[NLAYERS * HIDDEN * HIDDEN]; // [l][k][j]
    __shared__ __align__(16) float sWin_t[2 * HIDDEN];               // [c][j]
    __shared__ __align__(16) float sBin[HIDDEN];                     // [j]
    __shared__ __align__(16) float sWout_t[HIDDEN * 4];              // [k][j], j=3 pad 0

    const int tid = threadIdx.x;

    #pragma unroll
    for (int i = tid; i < NLAYERS * 256; i += THREADS) {
        int l = i >> 8, r = i & 255, j = r >> 4, k = r & 15;
        sWh_t[(l * 16 + k) * 16 + j] = W_h[i];      // i = l*256 + j*16 + k
    }
    if (tid < 32)      { int j = tid >> 1, c = tid & 1; sWin_t[c * 16 + j] = W_in[j * 2 + c]; }
    else if (tid < 48) { sBin[tid - 32] = b_in[tid - 32]; }
    else if (tid < 112){ int i = tid - 48; int k = i >> 2, j = i & 3;
                         sWout_t[i] = (j < 3) ? W_out[j * 16 + k] : 0.0f; }
    __syncthreads();

    const int base = blockIdx.x * PTS_PER_BLOCK + tid;
    const bool full = (blockIdx.x != gridDim.x - 1);   // uniform branch

    const float2* __restrict__ xp = (const float2*)x;
    float2 xv[NPTS];
    #pragma unroll
    for (int p = 0; p < NPTS; p++) {
        int pt = base + p * THREADS;
        xv[p] = (full || pt < n_points) ? xp[pt] : make_float2(0.0f, 0.0f);
    }

    // ---- input layer: acc[p][jj] accumulates outputs (2j, 2j+1) ----
    float h[NPTS][HIDDEN];
    {
        const u64* __restrict__ w0 = (const u64*)&sWin_t[0];
        const u64* __restrict__ w1 = (const u64*)&sWin_t[16];
        const u64* __restrict__ bb = (const u64*)&sBin[0];
        #pragma unroll
        for (int p = 0; p < NPTS; p++) {
            u64 x0 = dup2(xv[p].x), x1 = dup2(xv[p].y);
            #pragma unroll
            for (int jj = 0; jj < 8; jj++) {
                u64 a = ffma2(x0, w0[jj], bb[jj]);
                a = ffma2(x1, w1[jj], a);
                float t0, t1; unpack2(a, t0, t1);
                h[p][2 * jj]     = tanh_hw(t0);
                h[p][2 * jj + 1] = tanh_hw(t1);
            }
        }
    }

    // ---- 8 hidden layers ----
    #pragma unroll 1
    for (int l = 0; l < NLAYERS; l++) {
        const ulonglong2* __restrict__ wl = (const ulonglong2*)&sWh_t[l * 256]; // [k*4 + jj2]
        u64 acc[NPTS][8];
        // k = 0
        {
            u64 w[8];
            #pragma unroll
            for (int jj2 = 0; jj2 < 4; jj2++) {
                ulonglong2 v = wl[jj2];
                w[2 * jj2] = v.x; w[2 * jj2 + 1] = v.y;
            }
            #pragma unroll
            for (int p = 0; p < NPTS; p++) {
                u64 hd = dup2(h[p][0]);
                #pragma unroll
                for (int jj = 0; jj < 8; jj++) acc[p][jj] = fmul2(hd, w[jj]);
            }
        }
        #pragma unroll
        for (int k = 1; k < HIDDEN; k++) {
            u64 w[8];
            #pragma unroll
            for (int jj2 = 0; jj2 < 4; jj2++) {
                ulonglong2 v = wl[k * 4 + jj2];
                w[2 * jj2] = v.x; w[2 * jj2 + 1] = v.y;
            }
            #pragma unroll
            for (int p = 0; p < NPTS; p++) {
                u64 hd = dup2(h[p][k]);
                #pragma unroll
                for (int jj = 0; jj < 8; jj++) acc[p][jj] = ffma2(hd, w[jj], acc[p][jj]);
            }
        }
        #pragma unroll
        for (int p = 0; p < NPTS; p++) {
            #pragma unroll
            for (int jj = 0; jj < 8; jj++) {
                float t0, t1; unpack2(acc[p][jj], t0, t1);
                h[p][2 * jj]     = tanh_hw(t0);
                h[p][2 * jj + 1] = tanh_hw(t1);
            }
        }
    }

    // ---- output layer: 16 -> 3 (padded to 4), sigmoid ----
    float o[NPTS][3];
    {
        u64 acc0[NPTS], acc1[NPTS];
        {
            ulonglong2 v = *(const ulonglong2*)&sWout_t[0];
            #pragma unroll
            for (int p = 0; p < NPTS; p++) {
                u64 hd = dup2(h[p][0]);
                acc0[p] = fmul2(hd, v.x);
                acc1[p] = fmul2(hd, v.y);
            }
        }
        #pragma unroll
        for (int k = 1; k < HIDDEN; k++) {
            ulonglong2 v = *(const ulonglong2*)&sWout_t[k * 4];
            #pragma unroll
            for (int p = 0; p < NPTS; p++) {
                u64 hd = dup2(h[p][k]);
                acc0[p] = ffma2(hd, v.x, acc0[p]);
                acc1[p] = ffma2(hd, v.y, acc1[p]);
            }
        }
        #pragma unroll
        for (int p = 0; p < NPTS; p++) {
            float a0, a1, a2, a3;
            unpack2(acc0[p], a0, a1);
            unpack2(acc1[p], a2, a3);
            o[p][0] = sigmoid_hw(a0);
            o[p][1] = sigmoid_hw(a1);
            o[p][2] = sigmoid_hw(a2);
        }
    }

    #pragma unroll
    for (int p = 0; p < NPTS; p++) {
        int pt = base + p * THREADS;
        if (full || pt < n_points) {
            out[pt * 3 + 0] = o[p][0];
            out[pt * 3 + 1] = o[p][1];
            out[pt * 3 + 2] = o[p][2];
        }
    }
}

extern "C" void kernel_launch(void* const* d_in, const int* in_sizes, int n_in,
                              void* d_out, int out_size) {
    const float* x     = (const float*)d_in[0];
    const float* W_in  = (const float*)d_in[1];
    const float* b_in  = (const float*)d_in[2];
    const float* W_h   = (const float*)d_in[3];
    const float* W_out = (const float*)d_in[4];
    float* out = (float*)d_out;

    int n_points = in_sizes[0] / 2;               // x is [N,2]
    int blocks = (n_points + PTS_PER_BLOCK - 1) / PTS_PER_BLOCK;  // 10923
    mlp_kernel<<<blocks, THREADS>>>(x, W_in, b_in, W_h, W_out, out, n_points);
}